// round 6
// baseline (speedup 1.0000x reference)
#include <cuda_runtime.h>
#include <cuda_bf16.h>
#include <math.h>
#include <stdint.h>

#define B_    8
#define NH    8
#define T_    8
#define HD    32
#define C_    256
#define N_    8192
#define HW    1024
#define BHT   512            // B*NH*T
#define M_TOT 65536          // B*N

typedef unsigned long long ull;

// ---------------- scratch (static device globals; no allocation) ----------------
__device__ float g_qn[(size_t)BHT * HW * HD];          //  67 MB : normalized q [bht][p][c]
__device__ float g_kn[(size_t)BHT * HD * HW];          //  67 MB : normalized shifted k [bht][c][p]
__device__ __nv_bfloat16 g_xhi[(size_t)M_TOT * C_];    //  34 MB
__device__ __nv_bfloat16 g_xlo[(size_t)M_TOT * C_];
__device__ __nv_bfloat16 g_vhi[(size_t)M_TOT * C_];
__device__ __nv_bfloat16 g_vlo[(size_t)M_TOT * C_];
__device__ __nv_bfloat16 g_wqk_hi[512 * 256];
__device__ __nv_bfloat16 g_wqk_lo[512 * 256];
__device__ __nv_bfloat16 g_wpj_hi[256 * 256];
__device__ __nv_bfloat16 g_wpj_lo[256 * 256];

// ======================= asm helpers ==================
__device__ __forceinline__ uint32_t smem_u32(const void* p) {
    uint32_t a;
    asm("{ .reg .u64 t; cvta.to.shared.u64 t, %1; cvt.u32.u64 %0, t; }" : "=r"(a) : "l"(p));
    return a;
}
__device__ __forceinline__ void cp16(uint32_t saddr, const void* g) {
    asm volatile("cp.async.cg.shared.global [%0], [%1], 16;" :: "r"(saddr), "l"(g));
}
#define CP_COMMIT() asm volatile("cp.async.commit_group;" ::: "memory")
#define CP_WAIT1()  asm volatile("cp.async.wait_group 1;" ::: "memory")

#define LDSM4(r0, r1, r2, r3, addr) \
    asm volatile("ldmatrix.sync.aligned.m8n8.x4.shared.b16 {%0,%1,%2,%3}, [%4];" \
                 : "=r"(r0), "=r"(r1), "=r"(r2), "=r"(r3) : "r"(addr))
#define MMA16816(c, a, b0, b1) \
    asm volatile("mma.sync.aligned.m16n8k16.row.col.f32.bf16.bf16.f32 " \
                 "{%0,%1,%2,%3},{%4,%5,%6,%7},{%8,%9},{%0,%1,%2,%3};" \
                 : "+f"((c)[0]), "+f"((c)[1]), "+f"((c)[2]), "+f"((c)[3]) \
                 : "r"((a)[0]), "r"((a)[1]), "r"((a)[2]), "r"((a)[3]), \
                   "r"(b0), "r"(b1))

// packed f32x2 FMA (Blackwell base ISA)
#define FMA2(d, a, b) \
    asm("fma.rn.f32x2 %0, %1, %2, %0;" : "+l"(d) : "l"(a), "l"(b))
__device__ __forceinline__ ull pack2(float x, float y) {
    ull r; asm("mov.b64 %0, {%1, %2};" : "=l"(r) : "f"(x), "f"(y)); return r;
}
__device__ __forceinline__ void unpack2(ull v, float& x, float& y) {
    asm("mov.b64 {%0, %1}, %2;" : "=f"(x), "=f"(y) : "l"(v));
}

// =================================================================================
// fp32 -> (bf16 hi, bf16 lo) split, vectorized
// =================================================================================
__global__ void __launch_bounds__(256)
conv_split(const float4* __restrict__ in, uint2* __restrict__ hi,
           uint2* __restrict__ lo, int n4)
{
    int i = blockIdx.x * 256 + threadIdx.x;
    if (i >= n4) return;
    float4 f = in[i];
    __nv_bfloat162 h0 = __floats2bfloat162_rn(f.x, f.y);
    __nv_bfloat162 h1 = __floats2bfloat162_rn(f.z, f.w);
    float r0 = f.x - __bfloat162float(__low2bfloat16(h0));
    float r1 = f.y - __bfloat162float(__high2bfloat16(h0));
    float r2 = f.z - __bfloat162float(__low2bfloat16(h1));
    float r3 = f.w - __bfloat162float(__high2bfloat16(h1));
    __nv_bfloat162 l0 = __floats2bfloat162_rn(r0, r1);
    __nv_bfloat162 l1 = __floats2bfloat162_rn(r2, r3);
    hi[i] = make_uint2(*(uint32_t*)&h0, *(uint32_t*)&h1);
    lo[i] = make_uint2(*(uint32_t*)&l0, *(uint32_t*)&l1);
}

// =================================================================================
// Shared GEMM machinery (unchanged from R5): 128x128 block, 3-stage cp.async,
// 3-term bf16 (Ahi*Bhi + Ahi*Blo + Alo*Bhi), B hi+lo in one LDSM4.
// =================================================================================
#define KGEMM 256
#define NTILES 8
#define GM_STAGE 32768
#define GM_SMEM  (3 * GM_STAGE)

__device__ __forceinline__ void stage_load(
    uint32_t sbase, const __nv_bfloat16* __restrict__ Ahi,
    const __nv_bfloat16* __restrict__ Alo, const __nv_bfloat16* __restrict__ Bhi,
    const __nv_bfloat16* __restrict__ Blo, int m0, int n0, int kt, int tid)
{
    int t = tid * 2;
    int row = t >> 2;
    int cb  = t & 3;
#pragma unroll
    for (int j = 0; j < 2; j++) {
        int c16 = cb + j;
        uint32_t soff = (uint32_t)(row * 64 + ((c16 ^ ((row >> 1) & 3)) << 4));
        size_t ga = (size_t)row * KGEMM + kt * 32 + c16 * 8;
        cp16(sbase +     0 + soff, Ahi + (size_t)m0 * KGEMM + ga);
        cp16(sbase +  8192 + soff, Alo + (size_t)m0 * KGEMM + ga);
        cp16(sbase + 16384 + soff, Bhi + (size_t)n0 * KGEMM + ga);
        cp16(sbase + 24576 + soff, Blo + (size_t)n0 * KGEMM + ga);
    }
}

__device__ __forceinline__ void gemm_mainloop(
    const __nv_bfloat16* __restrict__ Ahi, const __nv_bfloat16* __restrict__ Alo,
    const __nv_bfloat16* __restrict__ Bhi, const __nv_bfloat16* __restrict__ Blo,
    uint32_t sb, int m0, int n0, int tid, int lane, int wm, int wn,
    float acc[4][4][4])
{
#pragma unroll
    for (int i = 0; i < 4; i++)
#pragma unroll
        for (int j = 0; j < 4; j++)
#pragma unroll
            for (int q = 0; q < 4; q++) acc[i][j][q] = 0.f;

    stage_load(sb,            Ahi, Alo, Bhi, Blo, m0, n0, 0, tid);
    CP_COMMIT();
    stage_load(sb + GM_STAGE, Ahi, Alo, Bhi, Blo, m0, n0, 1, tid);
    CP_COMMIT();

    const uint32_t l2 = lane & 15;
    const uint32_t bsel = (lane & 16) ? 8192u : 0u;

    int stage = 0;
    int lstage = 2;
    for (int kt = 0; kt < NTILES; kt++) {
        CP_WAIT1();
        __syncthreads();
        if (kt + 2 < NTILES)
            stage_load(sb + lstage * GM_STAGE, Ahi, Alo, Bhi, Blo, m0, n0, kt + 2, tid);
        CP_COMMIT();
        lstage = stage;

        const uint32_t sa = sb + stage * GM_STAGE;
        stage = (stage == 2) ? 0 : stage + 1;

#pragma unroll
        for (int ks = 0; ks < 2; ks++) {
            uint32_t aaddr[4], baddr[4];
            {
                uint32_t achk = (uint32_t)(ks * 2) + (lane >> 4);
#pragma unroll
                for (int i = 0; i < 4; i++) {
                    uint32_t r = wm + l2 + i * 16;
                    aaddr[i] = sa + r * 64 + ((achk ^ ((r >> 1) & 3)) << 4);
                }
                uint32_t bchk = (uint32_t)(ks * 2) + ((l2 >> 3) & 1);
#pragma unroll
                for (int j = 0; j < 4; j++) {
                    uint32_t r = wn + (l2 & 7) + j * 8;
                    baddr[j] = sa + 16384 + r * 64 + ((bchk ^ ((r >> 1) & 3)) << 4) + bsel;
                }
            }
            uint32_t a[4][4], al[4][4], b4[4][4];
#pragma unroll
            for (int i = 0; i < 4; i++) LDSM4(a[i][0], a[i][1], a[i][2], a[i][3], aaddr[i]);
#pragma unroll
            for (int j = 0; j < 4; j++) LDSM4(b4[j][0], b4[j][1], b4[j][2], b4[j][3], baddr[j]);
#pragma unroll
            for (int i = 0; i < 4; i++) LDSM4(al[i][0], al[i][1], al[i][2], al[i][3], aaddr[i] + 8192);
#pragma unroll
            for (int i = 0; i < 4; i++)
#pragma unroll
                for (int j = 0; j < 4; j++) MMA16816(acc[i][j], a[i], b4[j][0], b4[j][1]);
#pragma unroll
            for (int i = 0; i < 4; i++)
#pragma unroll
                for (int j = 0; j < 4; j++) MMA16816(acc[i][j], a[i], b4[j][2], b4[j][3]);
#pragma unroll
            for (int i = 0; i < 4; i++)
#pragma unroll
                for (int j = 0; j < 4; j++) MMA16816(acc[i][j], al[i], b4[j][0], b4[j][1]);
        }
    }
}

// =================================================================================
// GEMM1 fused: qk GEMM + L2-normalize + temporal shift + relayout.
// k-CTAs whose frame tt==0 produce dead output -> early exit.
// =================================================================================
__global__ void __launch_bounds__(256, 2)
gemm_qk(const __nv_bfloat16* __restrict__ Ahi, const __nv_bfloat16* __restrict__ Alo,
        const __nv_bfloat16* __restrict__ Bhi, const __nv_bfloat16* __restrict__ Blo,
        float* __restrict__ qn, float* __restrict__ kn)
{
    const bool is_k = (blockIdx.x >= 2);
    const int tt_blk = (blockIdx.y >> 3) & 7;
    if (is_k && tt_blk == 0) return;        // dead k tile (shifted away)

    extern __shared__ char smg[];
    const uint32_t sb = smem_u32(smg);
    const int tid = threadIdx.x;
    const int lane = tid & 31;
    const int wid = tid >> 5;
    const int m0 = blockIdx.y * 128;
    const int n0 = blockIdx.x * 128;
    const int wm = (wid >> 2) * 64;
    const int wn = (wid & 3) * 32;

    float acc[4][4][4];
    gemm_mainloop(Ahi, Alo, Bhi, Blo, sb, m0, n0, tid, lane, wm, wn, acc);

    const int head = (((n0 & 255) + wn) >> 5);

#pragma unroll
    for (int i = 0; i < 4; i++) {
#pragma unroll
        for (int h = 0; h < 2; h++) {
            float v0[4], v1[4];
            float ss = 0.f;
#pragma unroll
            for (int j = 0; j < 4; j++) {
                v0[j] = acc[i][j][2 * h];
                v1[j] = acc[i][j][2 * h + 1];
                ss += v0[j] * v0[j] + v1[j] * v1[j];
            }
            ss += __shfl_xor_sync(0xffffffffu, ss, 1);
            ss += __shfl_xor_sync(0xffffffffu, ss, 2);
            float inv = 1.0f / fmaxf(sqrtf(ss), 1e-12f);

            int r = m0 + wm + i * 16 + (lane >> 2) + h * 8;
            int b  = r >> 13;
            int tt = (r >> 10) & 7;
            int p  = r & 1023;

            if (!is_k) {
                int bht = b * 64 + head * 8 + tt;
                float* dst = qn + ((size_t)bht * HW + p) * 32;
#pragma unroll
                for (int j = 0; j < 4; j++) {
                    int cin = j * 8 + (lane & 3) * 2;
                    *(float2*)(dst + cin) = make_float2(v0[j] * inv, v1[j] * inv);
                }
            } else {
                if (tt >= 1) {
                    int bht = b * 64 + head * 8 + (tt - 1);
                    float* dst = kn + (size_t)bht * 32 * HW + p;
#pragma unroll
                    for (int j = 0; j < 4; j++) {
                        int cin = j * 8 + (lane & 3) * 2;
                        dst[(size_t)cin * HW]       = v0[j] * inv;
                        dst[(size_t)(cin + 1) * HW] = v1[j] * inv;
                    }
                }
                if (tt == 7) {
                    int bht = b * 64 + head * 8 + 7;
                    float* dst = kn + (size_t)bht * 32 * HW + p;
#pragma unroll
                    for (int j = 0; j < 4; j++) {
                        int cin = j * 8 + (lane & 3) * 2;
                        dst[(size_t)cin * HW]       = v0[j] * inv;
                        dst[(size_t)(cin + 1) * HW] = v1[j] * inv;
                    }
                }
            }
        }
    }
}

// =================================================================================
// GEMM4: out = v @ w_proj^T + bias, fp32 out
// =================================================================================
__global__ void __launch_bounds__(256, 2)
gemm_proj(const __nv_bfloat16* __restrict__ Ahi, const __nv_bfloat16* __restrict__ Alo,
          const __nv_bfloat16* __restrict__ Bhi, const __nv_bfloat16* __restrict__ Blo,
          const float* __restrict__ bias, float* __restrict__ C, int ldc)
{
    extern __shared__ char smg[];
    const uint32_t sb = smem_u32(smg);
    const int tid = threadIdx.x;
    const int lane = tid & 31;
    const int wid = tid >> 5;
    const int m0 = blockIdx.y * 128;
    const int n0 = blockIdx.x * 128;
    const int wm = (wid >> 2) * 64;
    const int wn = (wid & 3) * 32;

    float acc[4][4][4];
    gemm_mainloop(Ahi, Alo, Bhi, Blo, sb, m0, n0, tid, lane, wm, wn, acc);

#pragma unroll
    for (int j = 0; j < 4; j++) {
        int c = n0 + wn + j * 8 + (lane & 3) * 2;
        float b0 = bias[c], b1 = bias[c + 1];
#pragma unroll
        for (int i = 0; i < 4; i++) {
            int r = m0 + wm + i * 16 + (lane >> 2);
            *(float2*)(C + (size_t)r * ldc + c) =
                make_float2(acc[i][j][0] + b0, acc[i][j][1] + b1);
            *(float2*)(C + (size_t)(r + 8) * ldc + c) =
                make_float2(acc[i][j][2] + b0, acc[i][j][3] + b1);
        }
    }
}

// =================================================================================
// Fused 7x7 correlation + (49->32) projection, packed f32x2 math throughout.
// k tile channel-pair interleaved (float2/LDS.64 per tap feeding 2 channels).
// =================================================================================
#define KCOLS 38
#define KROWS 14
#define KCH2  (KROWS * KCOLS)                     // 532 float2 per cpair
#define CORR_SMEM_BYTES (16 * KCH2 * 8 + 49 * 16 * 8 + 128)   // 74496

__global__ void __launch_bounds__(256, 2)
corr_kernel(const float* __restrict__ qn, const float* __restrict__ kn,
            const float* __restrict__ wc, const float* __restrict__ bc,
            __nv_bfloat16* __restrict__ vhi, __nv_bfloat16* __restrict__ vlo)
{
    extern __shared__ float2 sh2[];
    float2* shk2 = sh2;                      // [16][14][38]
    float2* shw2 = sh2 + 16 * KCH2;          // [49][16] : (w[2e][j], w[2e+1][j])
    float*  shb  = (float*)(shw2 + 49 * 16); // 32

    const int tid = threadIdx.x;
    const int img = blockIdx.x >> 2;
    const int yq  = (blockIdx.x & 3) * 8;

    for (int i = tid; i < 16 * KCH2; i += 256) shk2[i] = make_float2(0.f, 0.f);
    for (int i = tid; i < 49 * 16; i += 256) {
        int j = i >> 4, e2 = i & 15;
        shw2[i] = make_float2(wc[(2 * e2) * 49 + j], wc[(2 * e2 + 1) * 49 + j]);
    }
    if (tid < 32) shb[tid] = bc[tid];
    __syncthreads();

    const float* ksrc = kn + (size_t)img * 32 * HW;
    for (int i = tid; i < 32 * 14 * 8; i += 256) {
        int c = i / 112, rem = i - (i / 112) * 112;
        int r = rem >> 3, x4 = rem & 7;
        int gy = yq - 3 + r;
        if (gy >= 0 && gy < 32) {
            float4 v = *(const float4*)(ksrc + (size_t)c * HW + gy * 32 + x4 * 4);
            float* base = (float*)(shk2 + (c >> 1) * KCH2 + r * KCOLS + 3 + x4 * 4) + (c & 1);
            base[0] = v.x; base[2] = v.y; base[4] = v.z; base[6] = v.w;
        }
    }
    __syncthreads();

    const int tx = tid & 31;
    const int ty = tid >> 5;
    const int p  = (yq + ty) * 32 + tx;
    const int t    = img & 7;
    const int head = (img >> 3) & 7;
    const int b    = img >> 6;

    // q as 16 packed f32x2
    ull q2[16];
    {
        const ull* qv = (const ull*)(qn + ((size_t)img * HW + p) * 32);
#pragma unroll
        for (int i = 0; i < 16; i++) q2[i] = qv[i];
    }
    ull v2[16];
#pragma unroll
    for (int e = 0; e < 16; e++) v2[e] = 0ull;

#pragma unroll 1
    for (int dy = 0; dy < 7; dy++) {
        ull cA[7];
#pragma unroll
        for (int d = 0; d < 7; d++) cA[d] = 0ull;
        const ull* base = (const ull*)(shk2 + (ty + dy) * KCOLS + tx);
#pragma unroll
        for (int cp = 0; cp < 16; cp++) {
            const ull* bp = base + cp * KCH2;
            ull qa = q2[cp];
#pragma unroll
            for (int dx = 0; dx < 7; dx++) FMA2(cA[dx], qa, bp[dx]);
        }
#pragma unroll
        for (int dx = 0; dx < 7; dx++) {
            float sx, sy;
            unpack2(cA[dx], sx, sy);
            ull s2 = pack2(sx + sy, sx + sy);
            const ull* wr = (const ull*)(shw2 + (dy * 7 + dx) * 16);
#pragma unroll
            for (int e = 0; e < 16; e++) FMA2(v2[e], s2, wr[e]);
        }
    }

    size_t gbase = ((size_t)b * N_ + t * HW + p) * C_ + head * 32;
    uint32_t hw[16], lw[16];
#pragma unroll
    for (int e2 = 0; e2 < 16; e2++) {
        float vx, vy;
        unpack2(v2[e2], vx, vy);
        float o0 = vx + shb[2 * e2 + 0];
        float o1 = vy + shb[2 * e2 + 1];
        __nv_bfloat162 hb = __floats2bfloat162_rn(o0, o1);
        float r0 = o0 - __bfloat162float(__low2bfloat16(hb));
        float r1 = o1 - __bfloat162float(__high2bfloat16(hb));
        __nv_bfloat162 lb = __floats2bfloat162_rn(r0, r1);
        hw[e2] = *(uint32_t*)&hb;
        lw[e2] = *(uint32_t*)&lb;
    }
#pragma unroll
    for (int s = 0; s < 4; s++) {
        *(uint4*)(vhi + gbase + s * 8) = make_uint4(hw[4*s], hw[4*s+1], hw[4*s+2], hw[4*s+3]);
        *(uint4*)(vlo + gbase + s * 8) = make_uint4(lw[4*s], lw[4*s+1], lw[4*s+2], lw[4*s+3]);
    }
}

// =================================================================================
extern "C" void kernel_launch(void* const* d_in, const int* in_sizes, int n_in,
                              void* d_out, int out_size)
{
    const float* x      = (const float*)d_in[0];
    const float* w_qk   = (const float*)d_in[1];
    const float* w_corr = (const float*)d_in[2];
    const float* b_corr = (const float*)d_in[3];
    const float* w_proj = (const float*)d_in[4];
    const float* b_proj = (const float*)d_in[5];
    float* out = (float*)d_out;

    float *qn, *kn;
    __nv_bfloat16 *xhi, *xlo, *vhi, *vlo, *wqh, *wql, *wph, *wpl;
    cudaGetSymbolAddress((void**)&qn,  g_qn);
    cudaGetSymbolAddress((void**)&kn,  g_kn);
    cudaGetSymbolAddress((void**)&xhi, g_xhi);
    cudaGetSymbolAddress((void**)&xlo, g_xlo);
    cudaGetSymbolAddress((void**)&vhi, g_vhi);
    cudaGetSymbolAddress((void**)&vlo, g_vlo);
    cudaGetSymbolAddress((void**)&wqh, g_wqk_hi);
    cudaGetSymbolAddress((void**)&wql, g_wqk_lo);
    cudaGetSymbolAddress((void**)&wph, g_wpj_hi);
    cudaGetSymbolAddress((void**)&wpl, g_wpj_lo);

    cudaFuncSetAttribute(gemm_qk,   cudaFuncAttributeMaxDynamicSharedMemorySize, GM_SMEM);
    cudaFuncSetAttribute(gemm_proj, cudaFuncAttributeMaxDynamicSharedMemorySize, GM_SMEM);
    cudaFuncSetAttribute(corr_kernel, cudaFuncAttributeMaxDynamicSharedMemorySize,
                         CORR_SMEM_BYTES);

    // 0) hi/lo splits
    conv_split<<<(M_TOT * C_ / 4 + 255) / 256, 256>>>((const float4*)x, (uint2*)xhi, (uint2*)xlo, M_TOT * C_ / 4);
    conv_split<<<(512 * 256 / 4 + 255) / 256, 256>>>((const float4*)w_qk, (uint2*)wqh, (uint2*)wql, 512 * 256 / 4);
    conv_split<<<(256 * 256 / 4 + 255) / 256, 256>>>((const float4*)w_proj, (uint2*)wph, (uint2*)wpl, 256 * 256 / 4);

    // 1) qk GEMM fused with normalize + temporal shift + relayout
    gemm_qk<<<dim3(4, 512), 256, GM_SMEM>>>(xhi, xlo, wqh, wql, qn, kn);

    // 2) fused 7x7 correlation + w_corr projection -> v (bf16 hi/lo)
    corr_kernel<<<BHT * 4, 256, CORR_SMEM_BYTES>>>(qn, kn, w_corr, b_corr, vhi, vlo);

    // 3) out = v @ w_proj^T + b_proj
    gemm_proj<<<dim3(2, 512), 256, GM_SMEM>>>(vhi, vlo, wph, wpl, b_proj, out, 256);
}

// round 7
// speedup vs baseline: 1.0057x; 1.0057x over previous
#include <cuda_runtime.h>
#include <cuda_bf16.h>
#include <math.h>
#include <stdint.h>

#define B_    8
#define NH    8
#define T_    8
#define HD    32
#define C_    256
#define N_    8192
#define HW    1024
#define BHT   512            // B*NH*T
#define M_TOT 65536          // B*N

// ---------------- scratch (static device globals; no allocation) ----------------
__device__ float g_qn[(size_t)BHT * HW * HD];          //  67 MB : normalized q [bht][p][c]
__device__ float g_kn[(size_t)BHT * HD * HW];          //  67 MB : normalized shifted k [bht][c][p]
__device__ __nv_bfloat16 g_xhi[(size_t)M_TOT * C_];    //  34 MB
__device__ __nv_bfloat16 g_xlo[(size_t)M_TOT * C_];
__device__ __nv_bfloat16 g_vhi[(size_t)M_TOT * C_];
__device__ __nv_bfloat16 g_vlo[(size_t)M_TOT * C_];
__device__ __nv_bfloat16 g_ch[(size_t)BHT * HW * 64];  //  67 MB : corr hi [img][px][64]
__device__ __nv_bfloat16 g_cl[(size_t)BHT * HW * 64];  //  67 MB : corr lo
__device__ __nv_bfloat16 g_wqk_hi[512 * 256];
__device__ __nv_bfloat16 g_wqk_lo[512 * 256];
__device__ __nv_bfloat16 g_wpj_hi[256 * 256];
__device__ __nv_bfloat16 g_wpj_lo[256 * 256];
__device__ __nv_bfloat16 g_wcT_hi[32 * 64];            // w_corr -> [e][j'=dy*8+dx] padded
__device__ __nv_bfloat16 g_wcT_lo[32 * 64];

// ======================= asm helpers ==================
__device__ __forceinline__ uint32_t smem_u32(const void* p) {
    uint32_t a;
    asm("{ .reg .u64 t; cvta.to.shared.u64 t, %1; cvt.u32.u64 %0, t; }" : "=r"(a) : "l"(p));
    return a;
}
__device__ __forceinline__ void cp16(uint32_t saddr, const void* g) {
    asm volatile("cp.async.cg.shared.global [%0], [%1], 16;" :: "r"(saddr), "l"(g));
}
#define CP_COMMIT() asm volatile("cp.async.commit_group;" ::: "memory")
#define CP_WAIT1()  asm volatile("cp.async.wait_group 1;" ::: "memory")
#define CP_WAIT0()  asm volatile("cp.async.wait_group 0;" ::: "memory")

#define LDSM4(r0, r1, r2, r3, addr) \
    asm volatile("ldmatrix.sync.aligned.m8n8.x4.shared.b16 {%0,%1,%2,%3}, [%4];" \
                 : "=r"(r0), "=r"(r1), "=r"(r2), "=r"(r3) : "r"(addr))
#define MMA16816(c, a, b0, b1) \
    asm volatile("mma.sync.aligned.m16n8k16.row.col.f32.bf16.bf16.f32 " \
                 "{%0,%1,%2,%3},{%4,%5,%6,%7},{%8,%9},{%0,%1,%2,%3};" \
                 : "+f"((c)[0]), "+f"((c)[1]), "+f"((c)[2]), "+f"((c)[3]) \
                 : "r"((a)[0]), "r"((a)[1]), "r"((a)[2]), "r"((a)[3]), \
                   "r"(b0), "r"(b1))

__device__ __forceinline__ void split_bf16x2(float a, float b, uint32_t& hi, uint32_t& lo) {
    __nv_bfloat162 hb = __floats2bfloat162_rn(a, b);
    float r0 = a - __bfloat162float(__low2bfloat16(hb));
    float r1 = b - __bfloat162float(__high2bfloat16(hb));
    __nv_bfloat162 lb = __floats2bfloat162_rn(r0, r1);
    hi = *(uint32_t*)&hb;
    lo = *(uint32_t*)&lb;
}

// =================================================================================
// fp32 -> (bf16 hi, bf16 lo) split, vectorized
// =================================================================================
__global__ void __launch_bounds__(256)
conv_split(const float4* __restrict__ in, uint2* __restrict__ hi,
           uint2* __restrict__ lo, int n4)
{
    int i = blockIdx.x * 256 + threadIdx.x;
    if (i >= n4) return;
    float4 f = in[i];
    uint32_t h0, l0, h1, l1;
    split_bf16x2(f.x, f.y, h0, l0);
    split_bf16x2(f.z, f.w, h1, l1);
    hi[i] = make_uint2(h0, h1);
    lo[i] = make_uint2(l0, l1);
}

// w_corr [32 e][49 j] -> padded transposed-ish [32 e][64 j'] with j' = dy*8+dx
__global__ void __launch_bounds__(256)
prep_w(const float* __restrict__ wc, __nv_bfloat16* __restrict__ wh,
       __nv_bfloat16* __restrict__ wl)
{
    int i = blockIdx.x * 256 + threadIdx.x;
    if (i >= 32 * 64) return;
    int e = i >> 6, jp = i & 63;
    int dy = jp >> 3, dx = jp & 7;
    float v = (dy < 7 && dx < 7) ? wc[e * 49 + dy * 7 + dx] : 0.f;
    __nv_bfloat16 h = __float2bfloat16(v);
    float r = v - __bfloat162float(h);
    wh[i] = h;
    wl[i] = __float2bfloat16(r);
}

// =================================================================================
// Shared GEMM machinery (proven): 128x128 block, 3-stage cp.async, K=256,
// 3-term bf16 (Ahi*Bhi + Ahi*Blo + Alo*Bhi), B hi+lo in one LDSM4.
// =================================================================================
#define KGEMM 256
#define NTILES 8
#define GM_STAGE 32768
#define GM_SMEM  (3 * GM_STAGE)

__device__ __forceinline__ void stage_load(
    uint32_t sbase, const __nv_bfloat16* __restrict__ Ahi,
    const __nv_bfloat16* __restrict__ Alo, const __nv_bfloat16* __restrict__ Bhi,
    const __nv_bfloat16* __restrict__ Blo, int m0, int n0, int kt, int tid)
{
    int t = tid * 2;
    int row = t >> 2;
    int cb  = t & 3;
#pragma unroll
    for (int j = 0; j < 2; j++) {
        int c16 = cb + j;
        uint32_t soff = (uint32_t)(row * 64 + ((c16 ^ ((row >> 1) & 3)) << 4));
        size_t ga = (size_t)row * KGEMM + kt * 32 + c16 * 8;
        cp16(sbase +     0 + soff, Ahi + (size_t)m0 * KGEMM + ga);
        cp16(sbase +  8192 + soff, Alo + (size_t)m0 * KGEMM + ga);
        cp16(sbase + 16384 + soff, Bhi + (size_t)n0 * KGEMM + ga);
        cp16(sbase + 24576 + soff, Blo + (size_t)n0 * KGEMM + ga);
    }
}

__device__ __forceinline__ void gemm_mainloop(
    const __nv_bfloat16* __restrict__ Ahi, const __nv_bfloat16* __restrict__ Alo,
    const __nv_bfloat16* __restrict__ Bhi, const __nv_bfloat16* __restrict__ Blo,
    uint32_t sb, int m0, int n0, int tid, int lane, int wm, int wn,
    float acc[4][4][4])
{
#pragma unroll
    for (int i = 0; i < 4; i++)
#pragma unroll
        for (int j = 0; j < 4; j++)
#pragma unroll
            for (int q = 0; q < 4; q++) acc[i][j][q] = 0.f;

    stage_load(sb,            Ahi, Alo, Bhi, Blo, m0, n0, 0, tid);
    CP_COMMIT();
    stage_load(sb + GM_STAGE, Ahi, Alo, Bhi, Blo, m0, n0, 1, tid);
    CP_COMMIT();

    const uint32_t l2 = lane & 15;
    const uint32_t bsel = (lane & 16) ? 8192u : 0u;

    int stage = 0;
    int lstage = 2;
    for (int kt = 0; kt < NTILES; kt++) {
        CP_WAIT1();
        __syncthreads();
        if (kt + 2 < NTILES)
            stage_load(sb + lstage * GM_STAGE, Ahi, Alo, Bhi, Blo, m0, n0, kt + 2, tid);
        CP_COMMIT();
        lstage = stage;

        const uint32_t sa = sb + stage * GM_STAGE;
        stage = (stage == 2) ? 0 : stage + 1;

#pragma unroll
        for (int ks = 0; ks < 2; ks++) {
            uint32_t aaddr[4], baddr[4];
            {
                uint32_t achk = (uint32_t)(ks * 2) + (lane >> 4);
#pragma unroll
                for (int i = 0; i < 4; i++) {
                    uint32_t r = wm + l2 + i * 16;
                    aaddr[i] = sa + r * 64 + ((achk ^ ((r >> 1) & 3)) << 4);
                }
                uint32_t bchk = (uint32_t)(ks * 2) + ((l2 >> 3) & 1);
#pragma unroll
                for (int j = 0; j < 4; j++) {
                    uint32_t r = wn + (l2 & 7) + j * 8;
                    baddr[j] = sa + 16384 + r * 64 + ((bchk ^ ((r >> 1) & 3)) << 4) + bsel;
                }
            }
            uint32_t a[4][4], al[4][4], b4[4][4];
#pragma unroll
            for (int i = 0; i < 4; i++) LDSM4(a[i][0], a[i][1], a[i][2], a[i][3], aaddr[i]);
#pragma unroll
            for (int j = 0; j < 4; j++) LDSM4(b4[j][0], b4[j][1], b4[j][2], b4[j][3], baddr[j]);
#pragma unroll
            for (int i = 0; i < 4; i++) LDSM4(al[i][0], al[i][1], al[i][2], al[i][3], aaddr[i] + 8192);
#pragma unroll
            for (int i = 0; i < 4; i++)
#pragma unroll
                for (int j = 0; j < 4; j++) MMA16816(acc[i][j], a[i], b4[j][0], b4[j][1]);
#pragma unroll
            for (int i = 0; i < 4; i++)
#pragma unroll
                for (int j = 0; j < 4; j++) MMA16816(acc[i][j], a[i], b4[j][2], b4[j][3]);
#pragma unroll
            for (int i = 0; i < 4; i++)
#pragma unroll
                for (int j = 0; j < 4; j++) MMA16816(acc[i][j], al[i], b4[j][0], b4[j][1]);
        }
    }
}

// =================================================================================
// GEMM1 fused: qk GEMM + L2-normalize + temporal shift + relayout.
// =================================================================================
__global__ void __launch_bounds__(256, 2)
gemm_qk(const __nv_bfloat16* __restrict__ Ahi, const __nv_bfloat16* __restrict__ Alo,
        const __nv_bfloat16* __restrict__ Bhi, const __nv_bfloat16* __restrict__ Blo,
        float* __restrict__ qn, float* __restrict__ kn)
{
    const bool is_k = (blockIdx.x >= 2);
    const int tt_blk = (blockIdx.y >> 3) & 7;
    if (is_k && tt_blk == 0) return;        // dead k tile (shifted away)

    extern __shared__ char smg[];
    const uint32_t sb = smem_u32(smg);
    const int tid = threadIdx.x;
    const int lane = tid & 31;
    const int wid = tid >> 5;
    const int m0 = blockIdx.y * 128;
    const int n0 = blockIdx.x * 128;
    const int wm = (wid >> 2) * 64;
    const int wn = (wid & 3) * 32;

    float acc[4][4][4];
    gemm_mainloop(Ahi, Alo, Bhi, Blo, sb, m0, n0, tid, lane, wm, wn, acc);

    const int head = (((n0 & 255) + wn) >> 5);

#pragma unroll
    for (int i = 0; i < 4; i++) {
#pragma unroll
        for (int h = 0; h < 2; h++) {
            float v0[4], v1[4];
            float ss = 0.f;
#pragma unroll
            for (int j = 0; j < 4; j++) {
                v0[j] = acc[i][j][2 * h];
                v1[j] = acc[i][j][2 * h + 1];
                ss += v0[j] * v0[j] + v1[j] * v1[j];
            }
            ss += __shfl_xor_sync(0xffffffffu, ss, 1);
            ss += __shfl_xor_sync(0xffffffffu, ss, 2);
            float inv = 1.0f / fmaxf(sqrtf(ss), 1e-12f);

            int r = m0 + wm + i * 16 + (lane >> 2) + h * 8;
            int b  = r >> 13;
            int tt = (r >> 10) & 7;
            int p  = r & 1023;

            if (!is_k) {
                int bht = b * 64 + head * 8 + tt;
                float* dst = qn + ((size_t)bht * HW + p) * 32;
#pragma unroll
                for (int j = 0; j < 4; j++) {
                    int cin = j * 8 + (lane & 3) * 2;
                    *(float2*)(dst + cin) = make_float2(v0[j] * inv, v1[j] * inv);
                }
            } else {
                if (tt >= 1) {
                    int bht = b * 64 + head * 8 + (tt - 1);
                    float* dst = kn + (size_t)bht * 32 * HW + p;
#pragma unroll
                    for (int j = 0; j < 4; j++) {
                        int cin = j * 8 + (lane & 3) * 2;
                        dst[(size_t)cin * HW]       = v0[j] * inv;
                        dst[(size_t)(cin + 1) * HW] = v1[j] * inv;
                    }
                }
                if (tt == 7) {
                    int bht = b * 64 + head * 8 + 7;
                    float* dst = kn + (size_t)bht * 32 * HW + p;
#pragma unroll
                    for (int j = 0; j < 4; j++) {
                        int cin = j * 8 + (lane & 3) * 2;
                        dst[(size_t)cin * HW]       = v0[j] * inv;
                        dst[(size_t)(cin + 1) * HW] = v1[j] * inv;
                    }
                }
            }
        }
    }
}

// =================================================================================
// GEMM4: out = v @ w_proj^T + bias, fp32 out
// =================================================================================
__global__ void __launch_bounds__(256, 2)
gemm_proj(const __nv_bfloat16* __restrict__ Ahi, const __nv_bfloat16* __restrict__ Alo,
          const __nv_bfloat16* __restrict__ Bhi, const __nv_bfloat16* __restrict__ Blo,
          const float* __restrict__ bias, float* __restrict__ C, int ldc)
{
    extern __shared__ char smg[];
    const uint32_t sb = smem_u32(smg);
    const int tid = threadIdx.x;
    const int lane = tid & 31;
    const int wid = tid >> 5;
    const int m0 = blockIdx.y * 128;
    const int n0 = blockIdx.x * 128;
    const int wm = (wid >> 2) * 64;
    const int wn = (wid & 3) * 32;

    float acc[4][4][4];
    gemm_mainloop(Ahi, Alo, Bhi, Blo, sb, m0, n0, tid, lane, wm, wn, acc);

#pragma unroll
    for (int j = 0; j < 4; j++) {
        int c = n0 + wn + j * 8 + (lane & 3) * 2;
        float b0 = bias[c], b1 = bias[c + 1];
#pragma unroll
        for (int i = 0; i < 4; i++) {
            int r = m0 + wm + i * 16 + (lane >> 2);
            *(float2*)(C + (size_t)r * ldc + c) =
                make_float2(acc[i][j][0] + b0, acc[i][j][1] + b1);
            *(float2*)(C + (size_t)(r + 8) * ldc + c) =
                make_float2(acc[i][j][2] + b0, acc[i][j][3] + b1);
        }
    }
}

// =================================================================================
// corr-only: 7x7 correlation, NO projection. Writes corr[img][px][64] bf16 hi/lo
// with j' = dy*8+dx, zeros at dx==7 and j'>=56. R5-style float2 math.
// =================================================================================
#define KCOLS 38
#define KROWS 14
#define KCH2  (KROWS * KCOLS)                     // 532 float2 per cpair
#define CORR_SMEM_BYTES (16 * KCH2 * 8)           // 68096

__global__ void __launch_bounds__(256, 3)
corr_kernel(const float* __restrict__ qn, const float* __restrict__ kn,
            __nv_bfloat16* __restrict__ ch, __nv_bfloat16* __restrict__ cl)
{
    extern __shared__ float2 sh2[];
    float2* shk2 = sh2;                      // [16][14][38]

    const int tid = threadIdx.x;
    const int img = blockIdx.x >> 2;
    const int yq  = (blockIdx.x & 3) * 8;

    for (int i = tid; i < 16 * KCH2; i += 256) shk2[i] = make_float2(0.f, 0.f);
    __syncthreads();

    const float* ksrc = kn + (size_t)img * 32 * HW;
    for (int i = tid; i < 32 * 14 * 8; i += 256) {
        int c = i / 112, rem = i - (i / 112) * 112;
        int r = rem >> 3, x4 = rem & 7;
        int gy = yq - 3 + r;
        if (gy >= 0 && gy < 32) {
            float4 v = *(const float4*)(ksrc + (size_t)c * HW + gy * 32 + x4 * 4);
            float* base = (float*)(shk2 + (c >> 1) * KCH2 + r * KCOLS + 3 + x4 * 4) + (c & 1);
            base[0] = v.x; base[2] = v.y; base[4] = v.z; base[6] = v.w;
        }
    }
    __syncthreads();

    const int tx = tid & 31;
    const int ty = tid >> 5;
    const int p  = (yq + ty) * 32 + tx;

    float2 q2[16];
    {
        const float4* qv = (const float4*)(qn + ((size_t)img * HW + p) * 32);
#pragma unroll
        for (int i = 0; i < 8; i++) {
            float4 f = qv[i];
            q2[2 * i]     = make_float2(f.x, f.y);
            q2[2 * i + 1] = make_float2(f.z, f.w);
        }
    }

    __nv_bfloat16* chp = ch + ((size_t)img * HW + p) * 64;
    __nv_bfloat16* clp = cl + ((size_t)img * HW + p) * 64;

#pragma unroll 1
    for (int dy = 0; dy < 7; dy++) {
        float2 cA[7];
#pragma unroll
        for (int d = 0; d < 7; d++) cA[d] = make_float2(0.f, 0.f);
        const float2* base = shk2 + (ty + dy) * KCOLS + tx;
#pragma unroll
        for (int cp = 0; cp < 16; cp++) {
            const float2* bp = base + cp * KCH2;
            float2 qa = q2[cp];
#pragma unroll
            for (int dx = 0; dx < 7; dx++) {
                float2 kv = bp[dx];
                cA[dx].x += qa.x * kv.x;
                cA[dx].y += qa.y * kv.y;
            }
        }
        float s[8];
#pragma unroll
        for (int d = 0; d < 7; d++) s[d] = cA[d].x + cA[d].y;
        s[7] = 0.f;
        uint32_t h4[4], l4[4];
#pragma unroll
        for (int q = 0; q < 4; q++) split_bf16x2(s[2 * q], s[2 * q + 1], h4[q], l4[q]);
        *(uint4*)(chp + dy * 8) = make_uint4(h4[0], h4[1], h4[2], h4[3]);
        *(uint4*)(clp + dy * 8) = make_uint4(l4[0], l4[1], l4[2], l4[3]);
    }
    // zero padding cols 56..63
    uint4 z = make_uint4(0, 0, 0, 0);
    *(uint4*)(chp + 56) = z;
    *(uint4*)(clp + 56) = z;
}

// =================================================================================
// proj_mma: v[px, e] = corr[px, 0..63] @ wcT[e, 0..63] + b_corr[e], 3-term bf16.
// Block = one image quarter (256 px). 8 warps, warp = 32 px (2 m16), N=32, K=64.
// A/B fragments via plain swizzled LDS.32 (no ldsm). Output -> vhi/vlo.
// =================================================================================
#define PJ_A_HI 0
#define PJ_A_LO 32768
#define PJ_W_HI 65536
#define PJ_W_LO (65536 + 4096)
#define PJ_SMEM (65536 + 8192)

__global__ void __launch_bounds__(256)
proj_mma(const __nv_bfloat16* __restrict__ ch, const __nv_bfloat16* __restrict__ cl,
         const __nv_bfloat16* __restrict__ wh, const __nv_bfloat16* __restrict__ wl,
         const float* __restrict__ bc,
         __nv_bfloat16* __restrict__ vhi, __nv_bfloat16* __restrict__ vlo)
{
    extern __shared__ char smp[];
    const uint32_t sb = smem_u32(smp);
    const int tid = threadIdx.x;
    const int lane = tid & 31;
    const int wid = tid >> 5;
    const int img = blockIdx.x >> 2;
    const int px0 = (blockIdx.x & 3) * 256;

    // stage A (256 px x 64 j, hi+lo) and w (32 e x 64 j, hi+lo), swizzled 16B chunks
    for (int i = tid; i < 2048; i += 256) {
        int px = i >> 3, chk = i & 7;
        uint32_t sw = (uint32_t)(px * 128 + ((chk ^ (px & 7)) << 4));
        size_t gofs = ((size_t)img * HW + px0 + px) * 64 + chk * 8;
        cp16(sb + PJ_A_HI + sw, ch + gofs);
        cp16(sb + PJ_A_LO + sw, cl + gofs);
    }
    if (tid < 256) {
        int r = tid >> 3, chk = tid & 7;
        uint32_t sw = (uint32_t)(r * 128 + ((chk ^ (r & 7)) << 4));
        cp16(sb + PJ_W_HI + sw, wh + r * 64 + chk * 8);
        cp16(sb + PJ_W_LO + sw, wl + r * 64 + chk * 8);
    }
    CP_COMMIT();
    CP_WAIT0();
    __syncthreads();

    const int wm = wid * 32;
    float acc[2][4][4];
#pragma unroll
    for (int m = 0; m < 2; m++)
#pragma unroll
        for (int n = 0; n < 4; n++)
#pragma unroll
            for (int q = 0; q < 4; q++) acc[m][n][q] = 0.f;

    const int lq = lane >> 2;       // 0..7
    const int lr = lane & 3;        // 0..3

#pragma unroll
    for (int k = 0; k < 4; k++) {
        // B fragments (w), 4 n8 tiles
        uint32_t bh[4][2], bl[4][2];
#pragma unroll
        for (int n = 0; n < 4; n++) {
            uint32_t row = n * 8 + lq;
            uint32_t o0 = row * 128 + (((2 * k)     ^ (row & 7)) << 4) + lr * 4;
            uint32_t o1 = row * 128 + (((2 * k + 1) ^ (row & 7)) << 4) + lr * 4;
            bh[n][0] = *(const uint32_t*)(smp + PJ_W_HI + o0);
            bh[n][1] = *(const uint32_t*)(smp + PJ_W_HI + o1);
            bl[n][0] = *(const uint32_t*)(smp + PJ_W_LO + o0);
            bl[n][1] = *(const uint32_t*)(smp + PJ_W_LO + o1);
        }
#pragma unroll
        for (int m = 0; m < 2; m++) {
            uint32_t r0 = wm + m * 16 + lq;
            uint32_t r1 = r0 + 8;
            uint32_t c0 = ((2 * k)     << 4);
            uint32_t c1 = ((2 * k + 1) << 4);
            uint32_t a00 = r0 * 128 + ((c0 >> 4 ^ (r0 & 7)) << 4) + lr * 4;
            uint32_t a10 = r1 * 128 + ((c0 >> 4 ^ (r1 & 7)) << 4) + lr * 4;
            uint32_t a01 = r0 * 128 + ((c1 >> 4 ^ (r0 & 7)) << 4) + lr * 4;
            uint32_t a11 = r1 * 128 + ((c1 >> 4 ^ (r1 & 7)) << 4) + lr * 4;
            uint32_t Ah[4], Al[4];
            Ah[0] = *(const uint32_t*)(smp + PJ_A_HI + a00);
            Ah[1] = *(const uint32_t*)(smp + PJ_A_HI + a10);
            Ah[2] = *(const uint32_t*)(smp + PJ_A_HI + a01);
            Ah[3] = *(const uint32_t*)(smp + PJ_A_HI + a11);
            Al[0] = *(const uint32_t*)(smp + PJ_A_LO + a00);
            Al[1] = *(const uint32_t*)(smp + PJ_A_LO + a10);
            Al[2] = *(const uint32_t*)(smp + PJ_A_LO + a01);
            Al[3] = *(const uint32_t*)(smp + PJ_A_LO + a11);
#pragma unroll
            for (int n = 0; n < 4; n++) {
                MMA16816(acc[m][n], Ah, bh[n][0], bh[n][1]);
                MMA16816(acc[m][n], Al, bh[n][0], bh[n][1]);
                MMA16816(acc[m][n], Ah, bl[n][0], bl[n][1]);
            }
        }
    }

    // epilogue: v + b_corr, split hi/lo, store bf16x2
    const int b    = img >> 6;
    const int head = (img >> 3) & 7;
    const int t    = img & 7;
#pragma unroll
    for (int n = 0; n < 4; n++) {
        int col = n * 8 + lr * 2;                   // e within head (0..31)
        float b0 = bc[col], b1 = bc[col + 1];
#pragma unroll
        for (int m = 0; m < 2; m++) {
            int px = px0 + wm + m * 16 + lq;
            size_t row0 = (size_t)b * N_ + t * HW + px;
            size_t row1 = row0 + 8;
            size_t g0 = row0 * C_ + head * 32 + col;
            size_t g1 = row1 * C_ + head * 32 + col;
            uint32_t h0, l0, h1, l1;
            split_bf16x2(acc[m][n][0] + b0, acc[m][n][1] + b1, h0, l0);
            split_bf16x2(acc[m][n][2] + b0, acc[m][n][3] + b1, h1, l1);
            *(uint32_t*)(vhi + g0) = h0;
            *(uint32_t*)(vlo + g0) = l0;
            *(uint32_t*)(vhi + g1) = h1;
            *(uint32_t*)(vlo + g1) = l1;
        }
    }
}

// =================================================================================
extern "C" void kernel_launch(void* const* d_in, const int* in_sizes, int n_in,
                              void* d_out, int out_size)
{
    const float* x      = (const float*)d_in[0];
    const float* w_qk   = (const float*)d_in[1];
    const float* w_corr = (const float*)d_in[2];
    const float* b_corr = (const float*)d_in[3];
    const float* w_proj = (const float*)d_in[4];
    const float* b_proj = (const float*)d_in[5];
    float* out = (float*)d_out;

    float *qn, *kn;
    __nv_bfloat16 *xhi, *xlo, *vhi, *vlo, *wqh, *wql, *wph, *wpl, *chp, *clp, *wch, *wcl;
    cudaGetSymbolAddress((void**)&qn,  g_qn);
    cudaGetSymbolAddress((void**)&kn,  g_kn);
    cudaGetSymbolAddress((void**)&xhi, g_xhi);
    cudaGetSymbolAddress((void**)&xlo, g_xlo);
    cudaGetSymbolAddress((void**)&vhi, g_vhi);
    cudaGetSymbolAddress((void**)&vlo, g_vlo);
    cudaGetSymbolAddress((void**)&wqh, g_wqk_hi);
    cudaGetSymbolAddress((void**)&wql, g_wqk_lo);
    cudaGetSymbolAddress((void**)&wph, g_wpj_hi);
    cudaGetSymbolAddress((void**)&wpl, g_wpj_lo);
    cudaGetSymbolAddress((void**)&chp, g_ch);
    cudaGetSymbolAddress((void**)&clp, g_cl);
    cudaGetSymbolAddress((void**)&wch, g_wcT_hi);
    cudaGetSymbolAddress((void**)&wcl, g_wcT_lo);

    cudaFuncSetAttribute(gemm_qk,   cudaFuncAttributeMaxDynamicSharedMemorySize, GM_SMEM);
    cudaFuncSetAttribute(gemm_proj, cudaFuncAttributeMaxDynamicSharedMemorySize, GM_SMEM);
    cudaFuncSetAttribute(corr_kernel, cudaFuncAttributeMaxDynamicSharedMemorySize,
                         CORR_SMEM_BYTES);
    cudaFuncSetAttribute(proj_mma, cudaFuncAttributeMaxDynamicSharedMemorySize, PJ_SMEM);

    // 0) hi/lo splits + w_corr prep
    conv_split<<<(M_TOT * C_ / 4 + 255) / 256, 256>>>((const float4*)x, (uint2*)xhi, (uint2*)xlo, M_TOT * C_ / 4);
    conv_split<<<(512 * 256 / 4 + 255) / 256, 256>>>((const float4*)w_qk, (uint2*)wqh, (uint2*)wql, 512 * 256 / 4);
    conv_split<<<(256 * 256 / 4 + 255) / 256, 256>>>((const float4*)w_proj, (uint2*)wph, (uint2*)wpl, 256 * 256 / 4);
    prep_w<<<8, 256>>>(w_corr, wch, wcl);

    // 1) qk GEMM fused with normalize + temporal shift + relayout
    gemm_qk<<<dim3(4, 512), 256, GM_SMEM>>>(xhi, xlo, wqh, wql, qn, kn);

    // 2) 7x7 correlation -> corr bf16 hi/lo
    corr_kernel<<<BHT * 4, 256, CORR_SMEM_BYTES>>>(qn, kn, chp, clp);

    // 3) projection (49->32) via mma -> v bf16 hi/lo
    proj_mma<<<BHT * 4, 256, PJ_SMEM>>>(chp, clp, wch, wcl, b_corr, vhi, vlo);

    // 4) out = v @ w_proj^T + b_proj
    gemm_proj<<<dim3(2, 512), 256, GM_SMEM>>>(vhi, vlo, wph, wpl, b_proj, out, 256);
}